// round 4
// baseline (speedup 1.0000x reference)
#include <cuda_runtime.h>
#include <math.h>

typedef unsigned long long u64;

#define NB   8
#define NV   2048
#define NP   32
#define NM   20
#define NPTS   (NB * NV * NP)         // 524288 points
#define NPAIRS (NPTS / 2)             // 262144... no: 8*2048*32/2 = 262144? (see below)

// NB*NV*NP = 8*2048*32 = 524288 points -> 262144 pairs
#undef NPAIRS
#define NPAIRS 262144

#define P1_BLOCKS 1024     // 16 v per block
#define P2_BLOCKS 2048     // 256 points per block

// Scratch (fully overwritten every launch -> deterministic)
__device__ float g_geomP[NPAIRS * 16];   // packed-pair records for pass1 (16 MB? 262144*16*4 = 16 MB)
__device__ float g_geomS[NPTS * 8];      // scalar per-point records for pass2 (16 MB)
__device__ float g_partial[P1_BLOCKS * 16];
__device__ float g_invnorm[NB * 16];

// ---------------- packed f32x2 helpers (Blackwell) ----------------
__device__ __forceinline__ u64 pk2(float lo, float hi) {
    u64 r; asm("mov.b64 %0, {%1,%2};" : "=l"(r) : "f"(lo), "f"(hi)); return r;
}
__device__ __forceinline__ void up2(u64 v, float& lo, float& hi) {
    asm("mov.b64 {%0,%1}, %2;" : "=f"(lo), "=f"(hi) : "l"(v));
}
__device__ __forceinline__ u64 fma2(u64 a, u64 b, u64 c) {
    u64 d; asm("fma.rn.f32x2 %0,%1,%2,%3;" : "=l"(d) : "l"(a), "l"(b), "l"(c)); return d;
}
__device__ __forceinline__ u64 mul2(u64 a, u64 b) {
    u64 d; asm("mul.rn.f32x2 %0,%1,%2;" : "=l"(d) : "l"(a), "l"(b)); return d;
}
__device__ __forceinline__ float ex2a(float x) {
    float r; asm("ex2.approx.f32 %0, %1;" : "=f"(r) : "f"(x)); return r;
}
__device__ __forceinline__ float rcpa(float x) {
    float r; asm("rcp.approx.f32 %0, %1;" : "=f"(r) : "f"(x)); return r;
}
__device__ __forceinline__ float rsqa(float x) {
    float r; asm("rsqrt.approx.f32 %0, %1;" : "=f"(r) : "f"(x)); return r;
}
__device__ __forceinline__ void stcs4(float4* p, float4 v) {
    asm volatile("st.global.cs.v4.f32 [%0], {%1,%2,%3,%4};"
                 :: "l"(p), "f"(v.x), "f"(v.y), "f"(v.z), "f"(v.w));
}

// shell constants: f_k = exp(32 r_k d - 16 r_k^2), r_k = k/3
#define SH_A1  15.3887470903f     // (32/3)*log2(e)
#define SH_B1  -2.5647911817f     // -(16/9)*log2(e)
#define SH_C1   0.1690133154f     // exp(-16/9)
#define SH_C2   8.1598804e-4f     // exp(-64/9)

// Horner-factored s = sum_j Y_j m_j, packed version (19 fma2)
#define POLY_S2(nx, ny, nz, s)                                                 \
    u64 pA = fma2(nz, fma2(nz, fma2(nz, Yp[3], Yp[2]), Yp[1]), Yp[0]);         \
    u64 pB = fma2(nz, fma2(nz, Yp[6], Yp[5]), Yp[4]);                          \
    u64 pC = fma2(nz, Yp[8], Yp[7]);                                           \
    u64 pD = fma2(nz, fma2(nz, Yp[12], Yp[11]), Yp[10]);                       \
    u64 pE = fma2(nz, Yp[14], Yp[13]);                                         \
    u64 pF = fma2(nz, Yp[17], Yp[16]);                                         \
    u64 pG = fma2(nx, Yp[19], fma2(ny, Yp[18], pF));                           \
    u64 pH = fma2(ny, Yp[15], pE);                                             \
    u64 pX = fma2(nx, pG, fma2(ny, pH, pD));                                   \
    u64 pT = fma2(ny, fma2(ny, fma2(ny, Yp[9], pC), pB), pA);                  \
    u64 s  = fma2(nx, pX, pT);

// Scalar version (19 fmaf)
__device__ __forceinline__ float poly_s1(const float* Yr, float nx, float ny, float nz) {
    float pA = fmaf(nz, fmaf(nz, fmaf(nz, Yr[3], Yr[2]), Yr[1]), Yr[0]);
    float pB = fmaf(nz, fmaf(nz, Yr[6], Yr[5]), Yr[4]);
    float pC = fmaf(nz, Yr[8], Yr[7]);
    float pD = fmaf(nz, fmaf(nz, Yr[12], Yr[11]), Yr[10]);
    float pE = fmaf(nz, Yr[14], Yr[13]);
    float pF = fmaf(nz, Yr[17], Yr[16]);
    float pG = fmaf(nx, Yr[19], fmaf(ny, Yr[18], pF));
    float pH = fmaf(ny, Yr[15], pE);
    float pX = fmaf(nx, pG, fmaf(ny, pH, pD));
    float pT = fmaf(ny, fmaf(ny, fmaf(ny, Yr[9], pC), pB), pA);
    return fmaf(nx, pX, pT);
}

// -------------------------------------------------------------------------
// prep: geometry per point, written in two layouts:
//   packed-pair (for pass1, f32x2 fields) and scalar per-point (for pass2)
// -------------------------------------------------------------------------
__device__ __forceinline__ void geom1(float x, float y, float z,
                                      float& nx, float& ny, float& nz,
                                      float& s0, float& s1, float& s2, float& s3)
{
    float r2 = fmaf(x, x, fmaf(y, y, z * z));
    float r2c = fmaxf(r2, 1e-12f);
    float rinv = rsqa(r2c);
    float d = r2c * rinv;                 // == sqrt(r2)
    nx = -x * rinv; ny = -y * rinv; nz = -z * rinv;
    float de = fminf(d, 1.0f);
    float f1 = ex2a(fmaf(de, SH_A1, SH_B1));
    float ft = f1 * SH_C1;
    float f2 = ft * ft;
    float f3 = f1 * f2 * SH_C2;
    float sum = 1.0f + f1 + f2 + f3;      // f0 == 1 -> sum >= 1, clamp inert
    float w = (r2 <= 1.0f) ? rcpa(sum) : 0.0f;
    s0 = w; s1 = f1 * w; s2 = f2 * w; s3 = f3 * w;
}

__global__ __launch_bounds__(256) void sh_prep(const float* __restrict__ patches)
{
    int pr = blockIdx.x * 256 + threadIdx.x;      // pair id
    const float2* q = (const float2*)patches + 3 * (size_t)pr;
    float2 q0 = __ldg(q + 0), q1 = __ldg(q + 1), q2 = __ldg(q + 2);
    float nxA, nyA, nzA, a0, a1, a2, a3;
    float nxB, nyB, nzB, b0, b1, b2, b3;
    geom1(q0.x, q0.y, q1.x, nxA, nyA, nzA, a0, a1, a2, a3);
    geom1(q1.y, q2.x, q2.y, nxB, nyB, nzB, b0, b1, b2, b3);

    float4* recP = (float4*)(g_geomP + (size_t)pr * 16);
    recP[0] = make_float4(nxA, nxB, nyA, nyB);
    recP[1] = make_float4(nzA, nzB, a0, b0);
    recP[2] = make_float4(a1, b1, a2, b2);
    recP[3] = make_float4(a3, b3, 0.0f, 0.0f);

    float4* recS = (float4*)(g_geomS + (size_t)pr * 16);
    recS[0] = make_float4(nxA, nyA, nzA, a0);
    recS[1] = make_float4(a1, a2, a3, 0.0f);
    recS[2] = make_float4(nxB, nyB, nzB, b0);
    recS[3] = make_float4(b1, b2, b3, 0.0f);
}

// -------------------------------------------------------------------------
// pass1: per (b,v,l,s) accumulate sum_p (shell_s*sh_i)^2 over i in l,
//        reduce to per-block partial of sum_v sqrt(.). Deterministic.
// -------------------------------------------------------------------------
__global__ __launch_bounds__(256) void sh_pass1(const float* __restrict__ Y)
{
    __shared__ float red[8][32][4];
    __shared__ float red2[16][16];

    int tid  = threadIdx.x;
    int warp = tid >> 5, lane = tid & 31;
    int hw   = lane >> 4, li = lane & 15;
    int gv   = blockIdx.x * 16 + warp * 2 + hw;

    u64 Yp[NM];
#pragma unroll
    for (int j = 0; j < NM; j++) { float yv = __ldg(Y + li * NM + j); Yp[j] = pk2(yv, yv); }

    u64 acc0 = 0ULL, acc1 = 0ULL, acc2 = 0ULL, acc3 = 0ULL;
    const ulonglong2* gb = (const ulonglong2*)(g_geomP + (size_t)gv * 16 * 16);

#pragma unroll
    for (int k = 0; k < 16; k++) {
        ulonglong2 r0 = __ldg(gb + 4 * k + 0);
        ulonglong2 r1 = __ldg(gb + 4 * k + 1);
        ulonglong2 r2 = __ldg(gb + 4 * k + 2);
        ulonglong2 r3 = __ldg(gb + 4 * k + 3);
        u64 nx = r0.x, ny = r0.y, nz = r1.x;
        u64 sw0 = r1.y, sw1 = r2.x, sw2 = r2.y, sw3 = r3.x;
        POLY_S2(nx, ny, nz, s)
        u64 t0 = mul2(sw0, s); acc0 = fma2(t0, t0, acc0);
        u64 t1 = mul2(sw1, s); acc1 = fma2(t1, t1, acc1);
        u64 t2 = mul2(sw2, s); acc2 = fma2(t2, t2, acc2);
        u64 t3 = mul2(sw3, s); acc3 = fma2(t3, t3, acc3);
    }

    float x0a,x0b,x1a,x1b,x2a,x2b,x3a,x3b;
    up2(acc0,x0a,x0b); up2(acc1,x1a,x1b); up2(acc2,x2a,x2b); up2(acc3,x3a,x3b);
    red[warp][lane][0] = x0a + x0b;
    red[warp][lane][1] = x1a + x1b;
    red[warp][lane][2] = x2a + x2b;
    red[warp][lane][3] = x3a + x3b;
    __syncthreads();

    {
        int vl = tid >> 4, ls = tid & 15;
        int l = ls >> 2, sdx = ls & 3;
        int w = vl >> 1, lb = (vl & 1) * 16;
        int lo, hi;
        if      (l == 0) { lo = 0; hi = 0;  }
        else if (l == 1) { lo = 1; hi = 3;  }
        else if (l == 2) { lo = 4; hi = 8;  }
        else             { lo = 9; hi = 15; }
        float sum = 0.f;
        for (int qq = lo; qq <= hi; qq++) sum += red[w][lb + qq][sdx];
        red2[vl][ls] = sqrtf(sum);
    }
    __syncthreads();

    if (tid < 16) {
        float t = 0.f;
#pragma unroll
        for (int vv = 0; vv < 16; vv++) t += red2[vv][tid];
        g_partial[blockIdx.x * 16 + tid] = t;
    }
}

// -------------------------------------------------------------------------
// pass1b: reduce 128 block-partials per batch -> invnorm[b][l][s]
// -------------------------------------------------------------------------
__global__ void sh_pass1b() {
    int t  = threadIdx.x;          // 128 threads: 8 b x 16 (l,s)
    int b  = t >> 4, ls = t & 15;
    float sum = 0.f;
    const int blocks_per_b = P1_BLOCKS / NB;   // 128
    for (int c = 0; c < blocks_per_b; c++)
        sum += g_partial[(b * blocks_per_b + c) * 16 + ls];
    float ml = fmaxf(sum * (1.0f / (float)NV), 1e-8f);
    g_invnorm[b * 16 + ls] = 1.0f / ml;
}

// -------------------------------------------------------------------------
// pass2 (scalar): thread = (point-stream gl, SH row i). ~44 regs -> high occ.
// Per iter: 2x LDG.128 (broadcast), 19 fmaf, 8 mul, 1 streaming STG.128.
// Warp writes 512B contiguous.
// -------------------------------------------------------------------------
__global__ __launch_bounds__(256) void sh_pass2(
    const float* __restrict__ Y, float* __restrict__ out)
{
    int tid = threadIdx.x;
    int i   = tid & 15;          // SH index
    int gl  = tid >> 4;          // point-stream within block (0..15)
    int l   = (i == 0) ? 0 : (i < 4) ? 1 : (i < 9) ? 2 : 3;
    int b   = blockIdx.x >> 8;   // 256 blocks per batch

    float Yr[NM];
#pragma unroll
    for (int j = 0; j < NM; j++) Yr[j] = __ldg(Y + i * NM + j);

    float4 inq = *reinterpret_cast<const float4*>(&g_invnorm[b * 16 + l * 4]);

    int ptBase = blockIdx.x * 256;     // 256 points per block
    float4* o4 = (float4*)out;

#pragma unroll 4
    for (int k = 0; k < 16; k++) {
        int pt = ptBase + k * 16 + gl;
        const float4* rec = (const float4*)(g_geomS + (size_t)pt * 8);
        float4 r0 = __ldg(rec + 0);
        float4 r1 = __ldg(rec + 1);
        float nx = r0.x, ny = r0.y, nz = r0.z;
        float sw0 = r0.w, sw1 = r1.x, sw2 = r1.y, sw3 = r1.z;
        float s = poly_s1(Yr, nx, ny, nz);
        float4 o;
        o.x = sw0 * s * inq.x;
        o.y = sw1 * s * inq.y;
        o.z = sw2 * s * inq.z;
        o.w = sw3 * s * inq.w;
        stcs4(o4 + (size_t)pt * 16 + i, o);
    }
}

extern "C" void kernel_launch(void* const* d_in, const int* in_sizes, int n_in,
                              void* d_out, int out_size) {
    const float* patches = (const float*)d_in[0];   // (8,2048,32,3)
    const float* Y       = (const float*)d_in[1];   // (16,20)
    float* out           = (float*)d_out;           // (8,2048,32,16,4)
    (void)in_sizes; (void)n_in; (void)out_size;

    sh_prep  <<<NPAIRS / 256, 256>>>(patches);
    sh_pass1 <<<P1_BLOCKS, 256>>>(Y);
    sh_pass1b<<<1, 128>>>();
    sh_pass2 <<<P2_BLOCKS, 256>>>(Y, out);
}